// round 7
// baseline (speedup 1.0000x reference)
#include <cuda_runtime.h>
#include <cstdint>

#define BB 8
#define NN 4096
#define DD 64
#define SS 1024
#define KK 64
#define HH 64
#define CO 128
#define NWORKB 140     // worker blocks; first 136 also do BQ+MLP
#define WPB 17         // query-workers per batch

typedef unsigned long long u64;

// -------- device scratch --------
__device__ int   g_fps[BB * SS];
__device__ int   g_prog[BB];
__device__ int   g_feat_done;
__device__ float g_T[BB * NN * HH];
__device__ float g_nxyz_fallback[BB * SS * 3];

// -------- smem layout (floats) --------
#define OFF_X    0
#define OFF_Y    4096
#define OFF_Z    8192
#define OFF_RED  12288   // 64 uints (2x16 parity, v+i)
#define OFF_W1X  12352   // 192
#define OFF_W2   12544   // 4096 (feat phase reuses as W1[3:])
#define OFF_W3   16640   // 8192
#define OFF_B2   24832   // 64 (feat phase reuses as b1)
#define OFF_B3   24896   // 128
#define OFF_NBRI 25024   // 1024 ints (16 warps x 64)
#define OFF_CNT  26048   // 16
#define OFF_QXYZ 26064   // 48
#define OFF_POOL 26112   // 2048 (8 groups x 256)
#define SMEM_FLOATS 28160

// ---------------- helpers ----------------
__device__ __forceinline__ u64 pk2(float lo, float hi) {
    u64 d; asm("mov.b64 %0, {%1, %2};" : "=l"(d) : "f"(lo), "f"(hi)); return d;
}
__device__ __forceinline__ void upk2(u64 v, float& lo, float& hi) {
    asm("mov.b64 {%0, %1}, %2;" : "=f"(lo), "=f"(hi) : "l"(v));
}
__device__ __forceinline__ u64 fma2(u64 a, u64 b, u64 c) {
    u64 d; asm("fma.rn.f32x2 %0, %1, %2, %3;" : "=l"(d) : "l"(a), "l"(b), "l"(c));
    return d;
}
__device__ __forceinline__ u64 add2(u64 a, u64 b) {
    u64 d; asm("add.rn.f32x2 %0, %1, %2;" : "=l"(d) : "l"(a), "l"(b)); return d;
}
__device__ __forceinline__ u64 mul2(u64 a, u64 b) {
    u64 d; asm("mul.rn.f32x2 %0, %1, %2;" : "=l"(d) : "l"(a), "l"(b)); return d;
}
__device__ __forceinline__ unsigned redux_max_u32(unsigned v) {
    unsigned d; asm("redux.sync.max.u32 %0, %1, 0xffffffff;" : "=r"(d) : "r"(v)); return d;
}
__device__ __forceinline__ unsigned redux_min_u32(unsigned v) {
    unsigned d; asm("redux.sync.min.u32 %0, %1, 0xffffffff;" : "=r"(d) : "r"(v)); return d;
}
__device__ __forceinline__ void st_release(int* p, int v) {
    asm volatile("st.release.gpu.s32 [%0], %1;" :: "l"(p), "r"(v) : "memory");
}
__device__ __forceinline__ int ld_acquire(const int* p) {
    int v; asm volatile("ld.acquire.gpu.s32 %0, [%1];" : "=r"(v) : "l"(p) : "memory");
    return v;
}
#define NAMED_BAR(id) asm volatile("bar.sync %0, 64;" :: "r"(id) : "memory")

// =====================================================================
// Fused persistent kernel. grid = 148 (one wave), block = 512.
// =====================================================================
__global__ __launch_bounds__(512) void fused_kernel(
    const float* __restrict__ x,  const float* __restrict__ pos,
    const float* __restrict__ W1, const float* __restrict__ b1,
    const float* __restrict__ W2, const float* __restrict__ b2,
    const float* __restrict__ W3, const float* __restrict__ b3,
    float* __restrict__ out, float* __restrict__ nxyz)
{
    extern __shared__ float sm[];
    int t = threadIdx.x, lane = t & 31, warp = t >> 5;

    if (blockIdx.x < BB) {
        // =========================== FPS ===========================
        int b = blockIdx.x;
        const float* p = pos + (size_t)b * NN * 3;
        float* sx = sm + OFF_X;
        float* sy = sm + OFF_Y;
        float* sz = sm + OFF_Z;
        unsigned* s_v = (unsigned*)(sm + OFF_RED);   // [2][16] parity
        unsigned* s_i = s_v + 32;

        for (int i = t; i < NN * 3; i += 512) {
            float v = p[i]; int n = i / 3, c = i - n * 3;
            if (c == 0) sx[n] = v; else if (c == 1) sy[n] = v; else sz[n] = v;
        }
        __syncthreads();

        const int base = t * 8;
        u64 cpx[4], cpy[4], cpz[4];
        float md[8];
#pragma unroll
        for (int q = 0; q < 4; q++) {
            cpx[q] = pk2(sx[base + 2 * q], sx[base + 2 * q + 1]);
            cpy[q] = pk2(sy[base + 2 * q], sy[base + 2 * q + 1]);
            cpz[q] = pk2(sz[base + 2 * q], sz[base + 2 * q + 1]);
        }
#pragma unroll
        for (int r = 0; r < 8; r++) md[r] = 1e10f;

        if (t == 0) {
            g_fps[b * SS] = 0;
            st_release(&g_prog[b], 0);
        }
        int last = 0;

        for (int s = 1; s < SS; s++) {
            float lx = sx[last], ly = sy[last], lz = sz[last];
            u64 nlx = pk2(-lx, -lx), nly = pk2(-ly, -ly), nlz = pk2(-lz, -lz);
#pragma unroll
            for (int q = 0; q < 4; q++) {
                // exact reference rounding: sub, square, ((xx+yy)+zz); no fma
                u64 dx = add2(cpx[q], nlx);
                u64 dy = add2(cpy[q], nly);
                u64 dz = add2(cpz[q], nlz);
                u64 d2 = add2(add2(mul2(dx, dx), mul2(dy, dy)), mul2(dz, dz));
                float dlo, dhi; upk2(d2, dlo, dhi);
                md[2 * q]     = fminf(md[2 * q], dlo);
                md[2 * q + 1] = fminf(md[2 * q + 1], dhi);
            }
            // shallow tree max + parallel index recovery
            float m01[4];
#pragma unroll
            for (int q = 0; q < 4; q++) m01[q] = fmaxf(md[2 * q], md[2 * q + 1]);
            float best = fmaxf(fmaxf(m01[0], m01[1]), fmaxf(m01[2], m01[3]));
            unsigned msk = 0;
#pragma unroll
            for (int r = 0; r < 8; r++) if (md[r] == best) msk |= (1u << r);
            int bi = base + __ffs(msk) - 1;

            int par = s & 1;
            unsigned vb = __float_as_uint(best);        // dist >= 0: bits monotonic
            unsigned mx = redux_max_u32(vb);
            unsigned ci = (vb == mx) ? (unsigned)bi : 0xffffffffu;
            unsigned mn = redux_min_u32(ci);
            if (lane == 0) { s_v[par * 16 + warp] = mx; s_i[par * 16 + warp] = mn; }
            __syncthreads();
            unsigned v2 = (lane < 16) ? s_v[par * 16 + lane] : 0u;
            unsigned i2 = (lane < 16) ? s_i[par * 16 + lane] : 0xffffffffu;
            unsigned m2 = redux_max_u32(v2);
            unsigned c2 = (v2 == m2) ? i2 : 0xffffffffu;
            last = (int)redux_min_u32(c2);
            if (t == 0) {
                g_fps[b * SS + s] = last;
                st_release(&g_prog[b], s);
            }
        }
        return;
    }

    // =========================== workers ===========================
    int wb = blockIdx.x - BB;   // 0..139

    // ---- phase 1: feat hoist T = x @ W1[3:,:] + b1 ----
    {
        float* sW = sm + OFF_W2;
        float* sbF = sm + OFF_B2;
        for (int i = t; i < DD * HH; i += 512) sW[i] = W1[3 * HH + i];
        if (t < HH) sbF[t] = b1[t];
        __syncthreads();

        for (int n = wb * 16 + warp; n < BB * NN; n += NWORKB * 16) {
            const float* xr = x + (size_t)n * DD;
            float xr0 = xr[lane];
            float xr1 = xr[lane + 32];
            float a0 = sbF[lane], a1 = sbF[lane + 32];
#pragma unroll
            for (int d = 0; d < 32; d++) {
                float xv = __shfl_sync(0xffffffffu, xr0, d);
                a0 += xv * sW[d * HH + lane];
                a1 += xv * sW[d * HH + 32 + lane];
            }
#pragma unroll
            for (int d = 0; d < 32; d++) {
                float xv = __shfl_sync(0xffffffffu, xr1, d);
                a0 += xv * sW[(32 + d) * HH + lane];
                a1 += xv * sW[(32 + d) * HH + 32 + lane];
            }
            g_T[(size_t)n * HH + lane]      = a0;
            g_T[(size_t)n * HH + 32 + lane] = a1;
        }
        __threadfence();
        __syncthreads();
        if (t == 0) atomicAdd(&g_feat_done, 1);
    }

    if (wb >= BB * WPB) return;   // 4 feat-only blocks retire

    int b = wb / WPB;
    int w = wb % WPB;

    // ---- phase 2: load cloud + MLP weights ----
    float* sx = sm + OFF_X;
    float* sy = sm + OFF_Y;
    float* sz = sm + OFF_Z;
    {
        const float* p = pos + (size_t)b * NN * 3;
        for (int i = t; i < NN * 3; i += 512) {
            float v = p[i]; int n = i / 3, c = i - n * 3;
            if (c == 0) sx[n] = v; else if (c == 1) sy[n] = v; else sz[n] = v;
        }
    }
    float* sW1x = sm + OFF_W1X;
    float* sW2  = sm + OFF_W2;
    float* sW3  = sm + OFF_W3;
    float* sb2  = sm + OFF_B2;
    float* sb3  = sm + OFF_B3;
    for (int i = t; i < 192;  i += 512) sW1x[i] = W1[i];
    for (int i = t; i < 4096; i += 512) sW2[i]  = W2[i];
    for (int i = t; i < 8192; i += 512) sW3[i]  = W3[i];
    if (t < 64)                sb2[t] = b2[t];
    if (t >= 64 && t < 192)    sb3[t - 64] = b3[t - 64];
    __syncthreads();
    if (t == 0) { while (ld_acquire(&g_feat_done) < NWORKB) { } }
    __syncthreads();

    int*   s_nbr  = (int*)(sm + OFF_NBRI);
    int*   s_cnt  = (int*)(sm + OFF_CNT);
    float* s_qxyz = sm + OFF_QXYZ;
    float* s_pool = sm + OFF_POOL;
    const float RR = (float)(0.2 * 0.2);

    int g   = t >> 6;       // MLP group 0..7
    int k   = t & 63;       // neighbor slot
    int lk  = k & 31;
    int wig = k >> 5;

    for (int j = 0; j < 4; j++) {
        // ---- BQ: warp per query (16 queries per j) ----
        int sQ = w + WPB * (16 * j + warp);
        if (sQ < SS) {
            if (lane == 0) { while (ld_acquire(&g_prog[b]) < sQ) { } }
            __syncwarp();
            int qi = 0;
            if (lane == 0) qi = ld_acquire(&g_fps[b * SS + sQ]);
            qi = __shfl_sync(0xffffffffu, qi, 0);
            float qx = sx[qi], qy = sy[qi], qz = sz[qi];
            if (lane == 0) {
                s_qxyz[warp * 3 + 0] = qx;
                s_qxyz[warp * 3 + 1] = qy;
                s_qxyz[warp * 3 + 2] = qz;
                int gq = b * SS + sQ;
                nxyz[gq * 3 + 0] = qx;
                nxyz[gq * 3 + 1] = qy;
                nxyz[gq * 3 + 2] = qz;
            }
            int count = 0;
            for (int c = 0; c < NN / 32; c++) {
                int i = c * 32 + lane;
                float dx = sx[i] - qx, dy = sy[i] - qy, dz = sz[i] - qz;
                float d2 = __fadd_rn(__fadd_rn(__fmul_rn(dx, dx), __fmul_rn(dy, dy)),
                                     __fmul_rn(dz, dz));
                bool hit = d2 < RR;
                unsigned m = __ballot_sync(0xffffffffu, hit);
                if (hit) {
                    int ofs = count + __popc(m & ((1u << lane) - 1u));
                    if (ofs < KK) s_nbr[warp * KK + ofs] = i;
                }
                count += __popc(m);
                if (count >= KK) break;
            }
            if (count > KK) count = KK;
            if (lane == 0) s_cnt[warp] = count;
            for (int q2 = count + lane; q2 < KK; q2 += 32) s_nbr[warp * KK + q2] = NN - 1;
        }
        __syncthreads();

        // ---- MLP: 2 sub-rounds x 8 groups of 64 threads ----
        for (int sub = 0; sub < 2; sub++) {
            int ql = sub * 8 + g;
            int sq = w + WPB * (16 * j + ql);
            if (sq < SS) {
                int cnt = s_cnt[ql];
                int n   = s_nbr[ql * KK + k];
                bool valid = (k < cnt);
                float qx = s_qxyz[ql * 3 + 0];
                float qy = s_qxyz[ql * 3 + 1];
                float qz = s_qxyz[ql * 3 + 2];
                float dx = sx[n] - qx, dy = sy[n] - qy, dz = sz[n] - qz;
                u64 dx2 = pk2(dx, dx), dy2 = pk2(dy, dy), dz2 = pk2(dz, dz);

                // ---- layers 1+2 fused over input halves (reg pressure) ----
                u64 acc[32];
#pragma unroll
                for (int jj = 0; jj < 32; jj++)
                    acc[jj] = pk2(sb2[2 * jj], sb2[2 * jj + 1]);

#pragma unroll
                for (int hf = 0; hf < 2; hf++) {
                    u64 hp[16];
                    const ulonglong2* Trow = (const ulonglong2*)
                        (g_T + ((size_t)(b * NN + n)) * HH + hf * 32);
#pragma unroll
                    for (int q = 0; q < 8; q++) {
                        ulonglong2 v = Trow[q];
                        hp[2 * q] = v.x; hp[2 * q + 1] = v.y;
                    }
                    const u64* w0 = (const u64*)(sW1x)       + hf * 16;
                    const u64* w1 = (const u64*)(sW1x + 64)  + hf * 16;
                    const u64* w2 = (const u64*)(sW1x + 128) + hf * 16;
#pragma unroll
                    for (int jj = 0; jj < 16; jj++) {
                        hp[jj] = fma2(dx2, w0[jj], hp[jj]);
                        hp[jj] = fma2(dy2, w1[jj], hp[jj]);
                        hp[jj] = fma2(dz2, w2[jj], hp[jj]);
                        float lo, hi; upk2(hp[jj], lo, hi);
                        hp[jj] = pk2(fmaxf(lo, 0.0f), fmaxf(hi, 0.0f));
                    }
                    // accumulate layer 2 for inputs [hf*32, hf*32+32)
#pragma unroll 4
                    for (int ii = 0; ii < 32; ii += 2) {
                        float lo, hi; upk2(hp[ii >> 1], lo, hi);
                        u64 aLo = pk2(lo, lo), aHi = pk2(hi, hi);
                        const ulonglong2* wa =
                            (const ulonglong2*)(sW2 + (hf * 32 + ii) * 64);
                        const ulonglong2* wbv =
                            (const ulonglong2*)(sW2 + (hf * 32 + ii + 1) * 64);
#pragma unroll
                        for (int q = 0; q < 16; q++) {
                            ulonglong2 wv = wa[q];
                            acc[2 * q]     = fma2(aLo, wv.x, acc[2 * q]);
                            acc[2 * q + 1] = fma2(aLo, wv.y, acc[2 * q + 1]);
                        }
#pragma unroll
                        for (int q = 0; q < 16; q++) {
                            ulonglong2 wv = wbv[q];
                            acc[2 * q]     = fma2(aHi, wv.x, acc[2 * q]);
                            acc[2 * q + 1] = fma2(aHi, wv.y, acc[2 * q + 1]);
                        }
                    }
                }
                // relu h2 in place (packed)
#pragma unroll
                for (int jj = 0; jj < 32; jj++) {
                    float lo, hi; upk2(acc[jj], lo, hi);
                    acc[jj] = pk2(fmaxf(lo, 0.0f), fmaxf(hi, 0.0f));
                }

                // ---- layer 3 (4 tiles of 32 ch) + masked distributed pool ----
                for (int tile = 0; tile < 4; tile++) {
                    u64 a3[16];
                    const float* bt = sb3 + tile * 32;
#pragma unroll
                    for (int jj = 0; jj < 16; jj++)
                        a3[jj] = pk2(bt[2 * jj], bt[2 * jj + 1]);
#pragma unroll 4
                    for (int ii = 0; ii < 64; ii += 2) {
                        float lo, hi; upk2(acc[ii >> 1], lo, hi);
                        u64 aLo = pk2(lo, lo), aHi = pk2(hi, hi);
                        const ulonglong2* wa =
                            (const ulonglong2*)(sW3 + ii * CO + tile * 32);
                        const ulonglong2* wbv =
                            (const ulonglong2*)(sW3 + (ii + 1) * CO + tile * 32);
#pragma unroll
                        for (int q = 0; q < 8; q++) {
                            ulonglong2 wv = wa[q];
                            a3[2 * q]     = fma2(aLo, wv.x, a3[2 * q]);
                            a3[2 * q + 1] = fma2(aLo, wv.y, a3[2 * q + 1]);
                        }
#pragma unroll
                        for (int q = 0; q < 8; q++) {
                            ulonglong2 wv = wbv[q];
                            a3[2 * q]     = fma2(aHi, wv.x, a3[2 * q]);
                            a3[2 * q + 1] = fma2(aHi, wv.y, a3[2 * q + 1]);
                        }
                    }
                    float v[32];
#pragma unroll
                    for (int jj = 0; jj < 16; jj++) {
                        float lo, hi; upk2(a3[jj], lo, hi);
                        v[2 * jj]     = valid ? lo : 0.0f;
                        v[2 * jj + 1] = valid ? hi : 0.0f;
                    }
#pragma unroll
                    for (int m = 16; m >= 1; m >>= 1) {
#pragma unroll 16
                        for (int jj = 0; jj < m; jj++) {
                            float xk = (lk & m) ? v[jj] : v[m + jj];
                            float r  = __shfl_xor_sync(0xffffffffu, xk, m);
                            v[jj] = fmaxf((lk & m) ? v[m + jj] : v[jj], r);
                        }
                    }
                    s_pool[g * 256 + wig * 128 + tile * 32 + lk] = v[0];
                }
            }
            NAMED_BAR(1 + g);
            if (sq < SS) {
                int gq = b * SS + sq;
                float* pl = s_pool + g * 256;
                out[(size_t)gq * CO + k]      = fmaxf(pl[k],      pl[128 + k]);
                out[(size_t)gq * CO + 64 + k] = fmaxf(pl[64 + k], pl[192 + k]);
            }
            NAMED_BAR(1 + g);
        }
        __syncthreads();
    }
}

// =====================================================================
// launch
// =====================================================================
extern "C" void kernel_launch(void* const* d_in, const int* in_sizes, int n_in,
                              void* d_out, int out_size)
{
    const float* x   = (const float*)d_in[0];
    const float* pos = (const float*)d_in[1];
    const float* W1  = (const float*)d_in[2];
    const float* b1  = (const float*)d_in[3];
    const float* W2  = (const float*)d_in[4];
    const float* b2  = (const float*)d_in[5];
    const float* W3  = (const float*)d_in[6];
    const float* b3  = (const float*)d_in[7];

    float* out = (float*)d_out;
    float* nxyz;
    if (out_size >= BB * SS * CO + BB * SS * 3) {
        nxyz = out + (size_t)BB * SS * CO;
    } else {
        cudaGetSymbolAddress((void**)&nxyz, g_nxyz_fallback);
    }

    const int smem = SMEM_FLOATS * (int)sizeof(float);   // ~110 KB
    cudaFuncSetAttribute(fused_kernel, cudaFuncAttributeMaxDynamicSharedMemorySize,
                         smem);

    fused_kernel<<<BB + NWORKB, 512, smem>>>(x, pos, W1, b1, W2, b2, W3, b3,
                                             out, nxyz);
}

// round 8
// speedup vs baseline: 1.1145x; 1.1145x over previous
#include <cuda_runtime.h>
#include <cstdint>

#define BB 8
#define NN 4096
#define DD 64
#define SS 1024
#define KK 64
#define HH 64
#define CO 128
#define NWORKB 140     // worker blocks; first 136 also do BQ+MLP
#define WPB 17         // query-workers per batch
#define NWARP 12       // warps per worker block
#define NGRP 6         // MLP groups per worker block

typedef unsigned long long u64;

// -------- device scratch --------
__device__ int   g_fps[BB * SS];
__device__ int   g_prog[BB];
__device__ int   g_feat_done;
__device__ float g_T[BB * NN * HH];
__device__ float g_nxyz_fallback[BB * SS * 3];

// -------- smem layout (floats) --------
#define OFF_X    0
#define OFF_Y    4096
#define OFF_Z    8192
#define OFF_RED  12288   // 64 uints (2x8 parity, v+i)
#define OFF_W1X  12352   // 192
#define OFF_W2   12544   // 4096 (feat phase reuses as W1[3:])
#define OFF_W3   16640   // 8192
#define OFF_B2   24832   // 64 (feat phase reuses as b1)
#define OFF_B3   24896   // 128
#define OFF_NBRI 25024   // 768 ints (12 warps x 64)
#define OFF_CNT  25792   // 16
#define OFF_QXYZ 25808   // 48
#define OFF_POOL 25856   // 1536 (6 groups x 256)
#define SMEM_FLOATS 27392

// ---------------- helpers ----------------
__device__ __forceinline__ u64 pk2(float lo, float hi) {
    u64 d; asm("mov.b64 %0, {%1, %2};" : "=l"(d) : "f"(lo), "f"(hi)); return d;
}
__device__ __forceinline__ void upk2(u64 v, float& lo, float& hi) {
    asm("mov.b64 {%0, %1}, %2;" : "=f"(lo), "=f"(hi) : "l"(v));
}
__device__ __forceinline__ u64 fma2(u64 a, u64 b, u64 c) {
    u64 d; asm("fma.rn.f32x2 %0, %1, %2, %3;" : "=l"(d) : "l"(a), "l"(b), "l"(c));
    return d;
}
__device__ __forceinline__ u64 add2(u64 a, u64 b) {
    u64 d; asm("add.rn.f32x2 %0, %1, %2;" : "=l"(d) : "l"(a), "l"(b)); return d;
}
__device__ __forceinline__ u64 mul2(u64 a, u64 b) {
    u64 d; asm("mul.rn.f32x2 %0, %1, %2;" : "=l"(d) : "l"(a), "l"(b)); return d;
}
__device__ __forceinline__ unsigned redux_max_u32(unsigned v) {
    unsigned d; asm("redux.sync.max.u32 %0, %1, 0xffffffff;" : "=r"(d) : "r"(v)); return d;
}
__device__ __forceinline__ unsigned redux_min_u32(unsigned v) {
    unsigned d; asm("redux.sync.min.u32 %0, %1, 0xffffffff;" : "=r"(d) : "r"(v)); return d;
}
__device__ __forceinline__ void st_release(int* p, int v) {
    asm volatile("st.release.gpu.s32 [%0], %1;" :: "l"(p), "r"(v) : "memory");
}
__device__ __forceinline__ int ld_acquire(const int* p) {
    int v; asm volatile("ld.acquire.gpu.s32 %0, [%1];" : "=r"(v) : "l"(p) : "memory");
    return v;
}
#define NAMED_BAR(id, cnt) asm volatile("bar.sync %0, %1;" :: "r"(id), "r"(cnt) : "memory")

// =====================================================================
// Fused persistent kernel. grid = 148 (one wave), block = 384.
// blocks 0..7   : FPS producer (8 active warps; warps 8-11 retire early)
// blocks 8..147 : feat hoist, then (first 136) BQ+MLP consumers
// =====================================================================
__global__ __launch_bounds__(384) void fused_kernel(
    const float* __restrict__ x,  const float* __restrict__ pos,
    const float* __restrict__ W1, const float* __restrict__ b1,
    const float* __restrict__ W2, const float* __restrict__ b2,
    const float* __restrict__ W3, const float* __restrict__ b3,
    float* __restrict__ out, float* __restrict__ nxyz)
{
    extern __shared__ float sm[];
    int t = threadIdx.x, lane = t & 31, warp = t >> 5;

    if (blockIdx.x < BB) {
        // =========================== FPS ===========================
        int b = blockIdx.x;
        const float* p = pos + (size_t)b * NN * 3;
        float* sx = sm + OFF_X;
        float* sy = sm + OFF_Y;
        float* sz = sm + OFF_Z;
        unsigned* s_v = (unsigned*)(sm + OFF_RED);   // [2][8] parity
        unsigned* s_i = s_v + 16;

        for (int i = t; i < NN * 3; i += 384) {
            float v = p[i]; int n = i / 3, c = i - n * 3;
            if (c == 0) sx[n] = v; else if (c == 1) sy[n] = v; else sz[n] = v;
        }
        __syncthreads();
        if (t >= 256) return;   // warps 8-11 done (helped load only)

        const int base = t * 16;
        u64 cpx[8], cpy[8], cpz[8];
        float md[16];
#pragma unroll
        for (int q = 0; q < 8; q++) {
            cpx[q] = pk2(sx[base + 2 * q], sx[base + 2 * q + 1]);
            cpy[q] = pk2(sy[base + 2 * q], sy[base + 2 * q + 1]);
            cpz[q] = pk2(sz[base + 2 * q], sz[base + 2 * q + 1]);
        }
#pragma unroll
        for (int r = 0; r < 16; r++) md[r] = 1e10f;

        if (t == 0) {
            g_fps[b * SS] = 0;
            st_release(&g_prog[b], 0);
        }
        int last = 0;

        for (int s = 1; s < SS; s++) {
            float lx = sx[last], ly = sy[last], lz = sz[last];
            u64 nlx = pk2(-lx, -lx), nly = pk2(-ly, -ly), nlz = pk2(-lz, -lz);
#pragma unroll
            for (int q = 0; q < 8; q++) {
                // exact reference rounding: sub, square, ((xx+yy)+zz); no fma
                u64 dx = add2(cpx[q], nlx);
                u64 dy = add2(cpy[q], nly);
                u64 dz = add2(cpz[q], nlz);
                u64 d2 = add2(add2(mul2(dx, dx), mul2(dy, dy)), mul2(dz, dz));
                float dlo, dhi; upk2(d2, dlo, dhi);
                md[2 * q]     = fminf(md[2 * q], dlo);
                md[2 * q + 1] = fminf(md[2 * q + 1], dhi);
            }
            // shallow tree max + parallel index recovery
            float m01[8];
#pragma unroll
            for (int q = 0; q < 8; q++) m01[q] = fmaxf(md[2 * q], md[2 * q + 1]);
            float a0 = fmaxf(m01[0], m01[1]), a1 = fmaxf(m01[2], m01[3]);
            float a2 = fmaxf(m01[4], m01[5]), a3 = fmaxf(m01[6], m01[7]);
            float best = fmaxf(fmaxf(a0, a1), fmaxf(a2, a3));
            unsigned msk = 0;
#pragma unroll
            for (int r = 0; r < 16; r++) if (md[r] == best) msk |= (1u << r);
            int bi = base + __ffs(msk) - 1;

            int par = s & 1;
            unsigned vb = __float_as_uint(best);        // dist >= 0: bits monotonic
            unsigned mx = redux_max_u32(vb);
            unsigned ci = (vb == mx) ? (unsigned)bi : 0xffffffffu;
            unsigned mn = redux_min_u32(ci);
            if (lane == 0) { s_v[par * 8 + warp] = mx; s_i[par * 8 + warp] = mn; }
            NAMED_BAR(15, 256);
            unsigned v2 = (lane < 8) ? s_v[par * 8 + lane] : 0u;
            unsigned i2 = (lane < 8) ? s_i[par * 8 + lane] : 0xffffffffu;
            unsigned m2 = redux_max_u32(v2);
            unsigned c2 = (v2 == m2) ? i2 : 0xffffffffu;
            last = (int)redux_min_u32(c2);
            if (t == 0) {
                g_fps[b * SS + s] = last;
                st_release(&g_prog[b], s);
            }
        }
        return;
    }

    // =========================== workers ===========================
    int wb = blockIdx.x - BB;   // 0..139

    // ---- phase 1: feat hoist T = x @ W1[3:,:] + b1 ----
    {
        float* sW = sm + OFF_W2;
        float* sbF = sm + OFF_B2;
        for (int i = t; i < DD * HH; i += 384) sW[i] = W1[3 * HH + i];
        if (t < HH) sbF[t] = b1[t];
        __syncthreads();

        for (int n = wb * NWARP + warp; n < BB * NN; n += NWORKB * NWARP) {
            const float* xr = x + (size_t)n * DD;
            float xr0 = xr[lane];
            float xr1 = xr[lane + 32];
            float a0 = sbF[lane], a1 = sbF[lane + 32];
#pragma unroll
            for (int d = 0; d < 32; d++) {
                float xv = __shfl_sync(0xffffffffu, xr0, d);
                a0 += xv * sW[d * HH + lane];
                a1 += xv * sW[d * HH + 32 + lane];
            }
#pragma unroll
            for (int d = 0; d < 32; d++) {
                float xv = __shfl_sync(0xffffffffu, xr1, d);
                a0 += xv * sW[(32 + d) * HH + lane];
                a1 += xv * sW[(32 + d) * HH + 32 + lane];
            }
            g_T[(size_t)n * HH + lane]      = a0;
            g_T[(size_t)n * HH + 32 + lane] = a1;
        }
        __threadfence();
        __syncthreads();
        if (t == 0) atomicAdd(&g_feat_done, 1);
    }

    if (wb >= BB * WPB) return;   // 4 feat-only blocks retire

    int b = wb / WPB;
    int w = wb % WPB;

    // ---- phase 2: load cloud + MLP weights ----
    float* sx = sm + OFF_X;
    float* sy = sm + OFF_Y;
    float* sz = sm + OFF_Z;
    {
        const float* p = pos + (size_t)b * NN * 3;
        for (int i = t; i < NN * 3; i += 384) {
            float v = p[i]; int n = i / 3, c = i - n * 3;
            if (c == 0) sx[n] = v; else if (c == 1) sy[n] = v; else sz[n] = v;
        }
    }
    float* sW1x = sm + OFF_W1X;
    float* sW2  = sm + OFF_W2;
    float* sW3  = sm + OFF_W3;
    float* sb2  = sm + OFF_B2;
    float* sb3  = sm + OFF_B3;
    for (int i = t; i < 192;  i += 384) sW1x[i] = W1[i];
    for (int i = t; i < 4096; i += 384) sW2[i]  = W2[i];
    for (int i = t; i < 8192; i += 384) sW3[i]  = W3[i];
    if (t < 64)                sb2[t] = b2[t];
    if (t >= 64 && t < 192)    sb3[t - 64] = b3[t - 64];
    __syncthreads();
    if (t == 0) {
        while (ld_acquire(&g_feat_done) < NWORKB) { __nanosleep(128); }
    }
    __syncthreads();

    int*   s_nbr  = (int*)(sm + OFF_NBRI);
    int*   s_cnt  = (int*)(sm + OFF_CNT);
    float* s_qxyz = sm + OFF_QXYZ;
    float* s_pool = sm + OFF_POOL;
    const float RR = (float)(0.2 * 0.2);

    int g   = t >> 6;       // MLP group 0..5
    int k   = t & 63;       // neighbor slot
    int lk  = k & 31;
    int wig = k >> 5;

    for (int j = 0; j < 6; j++) {
        // ---- BQ: warp per query (12 queries per round) ----
        int sQ = w + WPB * (NWARP * j + warp);
        if (sQ < SS) {
            if (lane == 0) {
                while (ld_acquire(&g_prog[b]) < sQ) { __nanosleep(64); }
            }
            __syncwarp();
            int qi = 0;
            if (lane == 0) qi = ld_acquire(&g_fps[b * SS + sQ]);
            qi = __shfl_sync(0xffffffffu, qi, 0);
            float qx = sx[qi], qy = sy[qi], qz = sz[qi];
            if (lane == 0) {
                s_qxyz[warp * 3 + 0] = qx;
                s_qxyz[warp * 3 + 1] = qy;
                s_qxyz[warp * 3 + 2] = qz;
                int gq = b * SS + sQ;
                nxyz[gq * 3 + 0] = qx;
                nxyz[gq * 3 + 1] = qy;
                nxyz[gq * 3 + 2] = qz;
            }
            int count = 0;
            for (int c = 0; c < NN / 32; c++) {
                int i = c * 32 + lane;
                float dx = sx[i] - qx, dy = sy[i] - qy, dz = sz[i] - qz;
                float d2 = __fadd_rn(__fadd_rn(__fmul_rn(dx, dx), __fmul_rn(dy, dy)),
                                     __fmul_rn(dz, dz));
                bool hit = d2 < RR;
                unsigned m = __ballot_sync(0xffffffffu, hit);
                if (hit) {
                    int ofs = count + __popc(m & ((1u << lane) - 1u));
                    if (ofs < KK) s_nbr[warp * KK + ofs] = i;
                }
                count += __popc(m);
                if (count >= KK) break;
            }
            if (count > KK) count = KK;
            if (lane == 0) s_cnt[warp] = count;
            for (int q2 = count + lane; q2 < KK; q2 += 32) s_nbr[warp * KK + q2] = NN - 1;
        }
        __syncthreads();

        // ---- MLP: 2 sub-rounds x 6 groups of 64 threads ----
        for (int sub = 0; sub < 2; sub++) {
            int ql = sub * NGRP + g;
            int sq = w + WPB * (NWARP * j + ql);
            if (sq < SS) {
                int cnt = s_cnt[ql];
                int n   = s_nbr[ql * KK + k];
                bool valid = (k < cnt);
                float qx = s_qxyz[ql * 3 + 0];
                float qy = s_qxyz[ql * 3 + 1];
                float qz = s_qxyz[ql * 3 + 2];
                float dx = sx[n] - qx, dy = sy[n] - qy, dz = sz[n] - qz;

                // layer 1 (R6 structure)
                u64 hp[32];
                const ulonglong2* Trow =
                    (const ulonglong2*)(g_T + ((size_t)(b * NN + n)) * HH);
#pragma unroll
                for (int q = 0; q < 16; q++) {
                    ulonglong2 v = Trow[q];
                    hp[2 * q] = v.x; hp[2 * q + 1] = v.y;
                }
                {
                    u64 dx2 = pk2(dx, dx), dy2 = pk2(dy, dy), dz2 = pk2(dz, dz);
                    const u64* w0 = (const u64*)(sW1x);
                    const u64* w1 = (const u64*)(sW1x + 64);
                    const u64* w2 = (const u64*)(sW1x + 128);
#pragma unroll
                    for (int jj = 0; jj < 32; jj++) {
                        hp[jj] = fma2(dx2, w0[jj], hp[jj]);
                        hp[jj] = fma2(dy2, w1[jj], hp[jj]);
                        hp[jj] = fma2(dz2, w2[jj], hp[jj]);
                    }
                }
                float h1[64];
#pragma unroll
                for (int jj = 0; jj < 32; jj++) {
                    float lo, hi; upk2(hp[jj], lo, hi);
                    h1[2 * jj]     = fmaxf(lo, 0.0f);
                    h1[2 * jj + 1] = fmaxf(hi, 0.0f);
                }

                // layer 2
                u64 acc[32];
#pragma unroll
                for (int jj = 0; jj < 32; jj++)
                    acc[jj] = pk2(sb2[2 * jj], sb2[2 * jj + 1]);
#pragma unroll 8
                for (int i = 0; i < 64; i++) {
                    u64 a2 = pk2(h1[i], h1[i]);
                    const ulonglong2* ww = (const ulonglong2*)(sW2 + i * 64);
#pragma unroll
                    for (int q = 0; q < 16; q++) {
                        ulonglong2 wv = ww[q];
                        acc[2 * q]     = fma2(a2, wv.x, acc[2 * q]);
                        acc[2 * q + 1] = fma2(a2, wv.y, acc[2 * q + 1]);
                    }
                }
                float h2[64];
#pragma unroll
                for (int jj = 0; jj < 32; jj++) {
                    float lo, hi; upk2(acc[jj], lo, hi);
                    h2[2 * jj]     = fmaxf(lo, 0.0f);
                    h2[2 * jj + 1] = fmaxf(hi, 0.0f);
                }

                // layer 3 + masked distributed max-pool
                for (int tile = 0; tile < 4; tile++) {
                    u64 a3[16];
                    const float* bt = sb3 + tile * 32;
#pragma unroll
                    for (int jj = 0; jj < 16; jj++)
                        a3[jj] = pk2(bt[2 * jj], bt[2 * jj + 1]);
#pragma unroll 8
                    for (int i = 0; i < 64; i++) {
                        u64 a2 = pk2(h2[i], h2[i]);
                        const ulonglong2* ww =
                            (const ulonglong2*)(sW3 + i * CO + tile * 32);
#pragma unroll
                        for (int q = 0; q < 8; q++) {
                            ulonglong2 wv = ww[q];
                            a3[2 * q]     = fma2(a2, wv.x, a3[2 * q]);
                            a3[2 * q + 1] = fma2(a2, wv.y, a3[2 * q + 1]);
                        }
                    }
                    float v[32];
#pragma unroll
                    for (int jj = 0; jj < 16; jj++) {
                        float lo, hi; upk2(a3[jj], lo, hi);
                        v[2 * jj]     = valid ? lo : 0.0f;
                        v[2 * jj + 1] = valid ? hi : 0.0f;
                    }
#pragma unroll
                    for (int m = 16; m >= 1; m >>= 1) {
#pragma unroll 16
                        for (int jj = 0; jj < m; jj++) {
                            float xk = (lk & m) ? v[jj] : v[m + jj];
                            float r  = __shfl_xor_sync(0xffffffffu, xk, m);
                            v[jj] = fmaxf((lk & m) ? v[m + jj] : v[jj], r);
                        }
                    }
                    s_pool[g * 256 + wig * 128 + tile * 32 + lk] = v[0];
                }
            }
            NAMED_BAR(1 + g, 64);
            if (sq < SS) {
                int gq = b * SS + sq;
                float* pl = s_pool + g * 256;
                out[(size_t)gq * CO + k]      = fmaxf(pl[k],      pl[128 + k]);
                out[(size_t)gq * CO + 64 + k] = fmaxf(pl[64 + k], pl[192 + k]);
            }
            NAMED_BAR(1 + g, 64);
        }
        __syncthreads();
    }
}

// =====================================================================
// launch
// =====================================================================
extern "C" void kernel_launch(void* const* d_in, const int* in_sizes, int n_in,
                              void* d_out, int out_size)
{
    const float* x   = (const float*)d_in[0];
    const float* pos = (const float*)d_in[1];
    const float* W1  = (const float*)d_in[2];
    const float* b1  = (const float*)d_in[3];
    const float* W2  = (const float*)d_in[4];
    const float* b2  = (const float*)d_in[5];
    const float* W3  = (const float*)d_in[6];
    const float* b3  = (const float*)d_in[7];

    float* out = (float*)d_out;
    float* nxyz;
    if (out_size >= BB * SS * CO + BB * SS * 3) {
        nxyz = out + (size_t)BB * SS * CO;
    } else {
        cudaGetSymbolAddress((void**)&nxyz, g_nxyz_fallback);
    }

    const int smem = SMEM_FLOATS * (int)sizeof(float);   // ~107 KB
    cudaFuncSetAttribute(fused_kernel, cudaFuncAttributeMaxDynamicSharedMemorySize,
                         smem);

    fused_kernel<<<BB + NWORKB, 384, smem>>>(x, pos, W1, b1, W2, b2, W3, b3,
                                             out, nxyz);
}

// round 9
// speedup vs baseline: 1.4009x; 1.2571x over previous
#include <cuda_runtime.h>
#include <cstdint>

#define BB 8
#define NN 4096
#define DD 64
#define SS 1024
#define KK 64
#define HH 64
#define CO 128
#define NWORKB 140     // worker blocks; first 136 also do BQ+MLP
#define WPB 17         // query-workers per batch

typedef unsigned long long u64;

// -------- device scratch --------
__device__ int   g_fps[BB * SS];
__device__ int   g_prog[BB];
__device__ int   g_feat_done;
__device__ float g_T[BB * NN * HH];
__device__ float g_nxyz_fallback[BB * SS * 3];

// -------- smem layout (floats) --------
#define OFF_C4   0       // 4096 float4 = 16384 floats
#define OFF_RED  16384   // 64 uints (2x8 parity, v+i)
#define OFF_W1X  16448   // 192
#define OFF_W2   16640   // 4096 (feat phase reuses as W1[3:])
#define OFF_W3   20736   // 8192
#define OFF_B2   28928   // 64 (feat phase reuses as b1)
#define OFF_B3   28992   // 128
#define OFF_NBRI 29120   // 512 ints (8 warps x 64)
#define OFF_CNT  29632   // 8
#define OFF_QXYZ 29640   // 24
#define OFF_POOL 29664   // 1024 (4 groups x 256)
#define SMEM_FLOATS 30688

// ---------------- helpers ----------------
__device__ __forceinline__ u64 pk2(float lo, float hi) {
    u64 d; asm("mov.b64 %0, {%1, %2};" : "=l"(d) : "f"(lo), "f"(hi)); return d;
}
__device__ __forceinline__ void upk2(u64 v, float& lo, float& hi) {
    asm("mov.b64 {%0, %1}, %2;" : "=f"(lo), "=f"(hi) : "l"(v));
}
__device__ __forceinline__ u64 fma2(u64 a, u64 b, u64 c) {
    u64 d; asm("fma.rn.f32x2 %0, %1, %2, %3;" : "=l"(d) : "l"(a), "l"(b), "l"(c));
    return d;
}
__device__ __forceinline__ u64 add2(u64 a, u64 b) {
    u64 d; asm("add.rn.f32x2 %0, %1, %2;" : "=l"(d) : "l"(a), "l"(b)); return d;
}
__device__ __forceinline__ u64 mul2(u64 a, u64 b) {
    u64 d; asm("mul.rn.f32x2 %0, %1, %2;" : "=l"(d) : "l"(a), "l"(b)); return d;
}
__device__ __forceinline__ unsigned redux_max_u32(unsigned v) {
    unsigned d; asm("redux.sync.max.u32 %0, %1, 0xffffffff;" : "=r"(d) : "r"(v)); return d;
}
__device__ __forceinline__ unsigned redux_min_u32(unsigned v) {
    unsigned d; asm("redux.sync.min.u32 %0, %1, 0xffffffff;" : "=r"(d) : "r"(v)); return d;
}
__device__ __forceinline__ void st_release(int* p, int v) {
    asm volatile("st.release.gpu.s32 [%0], %1;" :: "l"(p), "r"(v) : "memory");
}
__device__ __forceinline__ int ld_acquire(const int* p) {
    int v; asm volatile("ld.acquire.gpu.s32 %0, [%1];" : "=r"(v) : "l"(p) : "memory");
    return v;
}
#define NAMED_BAR(id) asm volatile("bar.sync %0, 64;" :: "r"(id) : "memory")

// =====================================================================
// Fused persistent kernel. grid = 148 (one wave), block = 256.
// blocks 0..7   : FPS producer (one batch each), publishes via g_prog
// blocks 8..147 : feat hoist, then (first 136) BQ+MLP consumers
// =====================================================================
__global__ __launch_bounds__(256, 1) void fused_kernel(
    const float* __restrict__ x,  const float* __restrict__ pos,
    const float* __restrict__ W1, const float* __restrict__ b1,
    const float* __restrict__ W2, const float* __restrict__ b2,
    const float* __restrict__ W3, const float* __restrict__ b3,
    float* __restrict__ out, float* __restrict__ nxyz)
{
    extern __shared__ float sm[];
    int t = threadIdx.x, lane = t & 31, warp = t >> 5;

    if (blockIdx.x < BB) {
        // =========================== FPS ===========================
        int b = blockIdx.x;
        const float* p = pos + (size_t)b * NN * 3;
        float4* c4 = (float4*)(sm + OFF_C4);
        unsigned* s_v = (unsigned*)(sm + OFF_RED);   // [2][8] parity
        unsigned* s_i = s_v + 16;

        for (int i = t; i < NN * 3; i += 256) {
            float v = p[i]; int n = i / 3, c = i - n * 3;
            ((float*)c4)[n * 4 + c] = v;
        }
        __syncthreads();

        const int base = t * 16;
        u64 cpx[8], cpy[8], cpz[8];
        float md[16];
#pragma unroll
        for (int q = 0; q < 8; q++) {
            float4 p0 = c4[base + 2 * q];
            float4 p1 = c4[base + 2 * q + 1];
            cpx[q] = pk2(p0.x, p1.x);
            cpy[q] = pk2(p0.y, p1.y);
            cpz[q] = pk2(p0.z, p1.z);
        }
#pragma unroll
        for (int r = 0; r < 16; r++) md[r] = 1e10f;

        if (t == 0) {
            g_fps[b * SS] = 0;
            st_release(&g_prog[b], 0);
        }
        int last = 0;

        for (int s = 1; s < SS; s++) {
            float4 lp = c4[last];                 // ONE dependent LDS.128
            u64 nlx = pk2(-lp.x, -lp.x), nly = pk2(-lp.y, -lp.y),
                nlz = pk2(-lp.z, -lp.z);
#pragma unroll
            for (int q = 0; q < 8; q++) {
                // exact reference rounding: sub, square, ((xx+yy)+zz); no fma
                u64 dx = add2(cpx[q], nlx);
                u64 dy = add2(cpy[q], nly);
                u64 dz = add2(cpz[q], nlz);
                u64 d2 = add2(add2(mul2(dx, dx), mul2(dy, dy)), mul2(dz, dz));
                float dlo, dhi; upk2(d2, dlo, dhi);
                md[2 * q]     = fminf(md[2 * q], dlo);
                md[2 * q + 1] = fminf(md[2 * q + 1], dhi);
            }
            // shallow tree max + parallel index recovery
            float m01[8];
#pragma unroll
            for (int q = 0; q < 8; q++) m01[q] = fmaxf(md[2 * q], md[2 * q + 1]);
            float a0 = fmaxf(m01[0], m01[1]), a1 = fmaxf(m01[2], m01[3]);
            float a2 = fmaxf(m01[4], m01[5]), a3 = fmaxf(m01[6], m01[7]);
            float best = fmaxf(fmaxf(a0, a1), fmaxf(a2, a3));
            unsigned msk = 0;
#pragma unroll
            for (int r = 0; r < 16; r++) if (md[r] == best) msk |= (1u << r);
            int bi = base + __ffs(msk) - 1;

            int par = s & 1;
            unsigned vb = __float_as_uint(best);        // dist >= 0: bits monotonic
            unsigned mx = redux_max_u32(vb);
            unsigned ci = (vb == mx) ? (unsigned)bi : 0xffffffffu;
            unsigned mn = redux_min_u32(ci);
            if (lane == 0) { s_v[par * 8 + warp] = mx; s_i[par * 8 + warp] = mn; }
            __syncthreads();
            unsigned v2 = (lane < 8) ? s_v[par * 8 + lane] : 0u;
            unsigned i2 = (lane < 8) ? s_i[par * 8 + lane] : 0xffffffffu;
            unsigned m2 = redux_max_u32(v2);
            unsigned c2 = (v2 == m2) ? i2 : 0xffffffffu;
            last = (int)redux_min_u32(c2);
            if (t == 0) {
                g_fps[b * SS + s] = last;
                st_release(&g_prog[b], s);
            }
        }
        return;
    }

    // =========================== workers ===========================
    int wb = blockIdx.x - BB;   // 0..139

    // ---- phase 1: feat hoist T = x @ W1[3:,:] + b1 ----
    {
        float* sW = sm + OFF_W2;
        float* sbF = sm + OFF_B2;
        for (int i = t; i < DD * HH; i += 256) sW[i] = W1[3 * HH + i];
        if (t < HH) sbF[t] = b1[t];
        __syncthreads();

        for (int n = wb * 8 + warp; n < BB * NN; n += NWORKB * 8) {
            const float* xr = x + (size_t)n * DD;
            float xr0 = xr[lane];
            float xr1 = xr[lane + 32];
            float a0 = sbF[lane], a1 = sbF[lane + 32];
#pragma unroll
            for (int d = 0; d < 32; d++) {
                float xv = __shfl_sync(0xffffffffu, xr0, d);
                a0 += xv * sW[d * HH + lane];
                a1 += xv * sW[d * HH + 32 + lane];
            }
#pragma unroll
            for (int d = 0; d < 32; d++) {
                float xv = __shfl_sync(0xffffffffu, xr1, d);
                a0 += xv * sW[(32 + d) * HH + lane];
                a1 += xv * sW[(32 + d) * HH + 32 + lane];
            }
            g_T[(size_t)n * HH + lane]      = a0;
            g_T[(size_t)n * HH + 32 + lane] = a1;
        }
        __threadfence();
        __syncthreads();
        if (t == 0) atomicAdd(&g_feat_done, 1);
    }

    if (wb >= BB * WPB) return;   // 4 feat-only blocks retire

    int b = wb / WPB;
    int w = wb % WPB;

    // ---- phase 2: load cloud (float4) + MLP weights ----
    float4* c4 = (float4*)(sm + OFF_C4);
    {
        const float* p = pos + (size_t)b * NN * 3;
        for (int i = t; i < NN * 3; i += 256) {
            float v = p[i]; int n = i / 3, c = i - n * 3;
            ((float*)c4)[n * 4 + c] = v;
        }
    }
    float* sW1x = sm + OFF_W1X;
    float* sW2  = sm + OFF_W2;
    float* sW3  = sm + OFF_W3;
    float* sb2  = sm + OFF_B2;
    float* sb3  = sm + OFF_B3;
    for (int i = t; i < 192;  i += 256) sW1x[i] = W1[i];
    for (int i = t; i < 4096; i += 256) sW2[i]  = W2[i];
    for (int i = t; i < 8192; i += 256) sW3[i]  = W3[i];
    if (t < 64)                sb2[t] = b2[t];
    if (t >= 64 && t < 192)    sb3[t - 64] = b3[t - 64];
    __syncthreads();
    if (t == 0) { while (ld_acquire(&g_feat_done) < NWORKB) { } }
    __syncthreads();

    int*   s_nbr  = (int*)(sm + OFF_NBRI);
    int*   s_cnt  = (int*)(sm + OFF_CNT);
    float* s_qxyz = sm + OFF_QXYZ;
    float* s_pool = sm + OFF_POOL;
    const float RR = (float)(0.2 * 0.2);

    int g   = t >> 6;       // MLP group 0..3
    int k   = t & 63;       // neighbor slot
    int lk  = k & 31;
    int wig = k >> 5;

    for (int j = 0; j < 8; j++) {
        // ---- BQ: warp per query (8 queries per round) ----
        int sQ = w + WPB * (8 * j + warp);
        if (sQ < SS) {
            if (lane == 0) { while (ld_acquire(&g_prog[b]) < sQ) { } }
            __syncwarp();
            int qi = 0;
            if (lane == 0) qi = ld_acquire(&g_fps[b * SS + sQ]);
            qi = __shfl_sync(0xffffffffu, qi, 0);
            float4 qp = c4[qi];
            float qx = qp.x, qy = qp.y, qz = qp.z;
            if (lane == 0) {
                s_qxyz[warp * 3 + 0] = qx;
                s_qxyz[warp * 3 + 1] = qy;
                s_qxyz[warp * 3 + 2] = qz;
                int gq = b * SS + sQ;
                nxyz[gq * 3 + 0] = qx;
                nxyz[gq * 3 + 1] = qy;
                nxyz[gq * 3 + 2] = qz;
            }
            int count = 0;
            for (int c = 0; c < NN / 32; c++) {
                int i = c * 32 + lane;
                float4 pv = c4[i];
                float dx = pv.x - qx, dy = pv.y - qy, dz = pv.z - qz;
                float d2 = __fadd_rn(__fadd_rn(__fmul_rn(dx, dx), __fmul_rn(dy, dy)),
                                     __fmul_rn(dz, dz));
                bool hit = d2 < RR;
                unsigned m = __ballot_sync(0xffffffffu, hit);
                if (hit) {
                    int ofs = count + __popc(m & ((1u << lane) - 1u));
                    if (ofs < KK) s_nbr[warp * KK + ofs] = i;
                }
                count += __popc(m);
                if (count >= KK) break;
            }
            if (count > KK) count = KK;
            if (lane == 0) s_cnt[warp] = count;
            for (int q2 = count + lane; q2 < KK; q2 += 32) s_nbr[warp * KK + q2] = NN - 1;
        }
        __syncthreads();

        // ---- MLP: 2 sub-rounds x 4 groups of 64 threads ----
        for (int sub = 0; sub < 2; sub++) {
            int ql = sub * 4 + g;
            int sq = w + WPB * (8 * j + ql);
            if (sq < SS) {
                int cnt = s_cnt[ql];
                int n   = s_nbr[ql * KK + k];
                bool valid = (k < cnt);
                float qx = s_qxyz[ql * 3 + 0];
                float qy = s_qxyz[ql * 3 + 1];
                float qz = s_qxyz[ql * 3 + 2];
                float4 pn = c4[n];
                float dx = pn.x - qx, dy = pn.y - qy, dz = pn.z - qz;

                // layer 1
                u64 hp[32];
                const ulonglong2* Trow =
                    (const ulonglong2*)(g_T + ((size_t)(b * NN + n)) * HH);
#pragma unroll
                for (int q = 0; q < 16; q++) {
                    ulonglong2 v = Trow[q];
                    hp[2 * q] = v.x; hp[2 * q + 1] = v.y;
                }
                {
                    u64 dx2 = pk2(dx, dx), dy2 = pk2(dy, dy), dz2 = pk2(dz, dz);
                    const u64* w0 = (const u64*)(sW1x);
                    const u64* w1 = (const u64*)(sW1x + 64);
                    const u64* w2 = (const u64*)(sW1x + 128);
#pragma unroll
                    for (int jj = 0; jj < 32; jj++) {
                        hp[jj] = fma2(dx2, w0[jj], hp[jj]);
                        hp[jj] = fma2(dy2, w1[jj], hp[jj]);
                        hp[jj] = fma2(dz2, w2[jj], hp[jj]);
                    }
                }
                float h1[64];
#pragma unroll
                for (int jj = 0; jj < 32; jj++) {
                    float lo, hi; upk2(hp[jj], lo, hi);
                    h1[2 * jj]     = fmaxf(lo, 0.0f);
                    h1[2 * jj + 1] = fmaxf(hi, 0.0f);
                }

                // layer 2
                u64 acc[32];
#pragma unroll
                for (int jj = 0; jj < 32; jj++)
                    acc[jj] = pk2(sb2[2 * jj], sb2[2 * jj + 1]);
#pragma unroll 8
                for (int i = 0; i < 64; i++) {
                    u64 a2 = pk2(h1[i], h1[i]);
                    const ulonglong2* ww = (const ulonglong2*)(sW2 + i * 64);
#pragma unroll
                    for (int q = 0; q < 16; q++) {
                        ulonglong2 wv = ww[q];
                        acc[2 * q]     = fma2(a2, wv.x, acc[2 * q]);
                        acc[2 * q + 1] = fma2(a2, wv.y, acc[2 * q + 1]);
                    }
                }
                float h2[64];
#pragma unroll
                for (int jj = 0; jj < 32; jj++) {
                    float lo, hi; upk2(acc[jj], lo, hi);
                    h2[2 * jj]     = fmaxf(lo, 0.0f);
                    h2[2 * jj + 1] = fmaxf(hi, 0.0f);
                }

                // layer 3 + masked distributed max-pool
                for (int tile = 0; tile < 4; tile++) {
                    u64 a3[16];
                    const float* bt = sb3 + tile * 32;
#pragma unroll
                    for (int jj = 0; jj < 16; jj++)
                        a3[jj] = pk2(bt[2 * jj], bt[2 * jj + 1]);
#pragma unroll 8
                    for (int i = 0; i < 64; i++) {
                        u64 a2 = pk2(h2[i], h2[i]);
                        const ulonglong2* ww =
                            (const ulonglong2*)(sW3 + i * CO + tile * 32);
#pragma unroll
                        for (int q = 0; q < 8; q++) {
                            ulonglong2 wv = ww[q];
                            a3[2 * q]     = fma2(a2, wv.x, a3[2 * q]);
                            a3[2 * q + 1] = fma2(a2, wv.y, a3[2 * q + 1]);
                        }
                    }
                    float v[32];
#pragma unroll
                    for (int jj = 0; jj < 16; jj++) {
                        float lo, hi; upk2(a3[jj], lo, hi);
                        v[2 * jj]     = valid ? lo : 0.0f;
                        v[2 * jj + 1] = valid ? hi : 0.0f;
                    }
#pragma unroll
                    for (int m = 16; m >= 1; m >>= 1) {
#pragma unroll 16
                        for (int jj = 0; jj < m; jj++) {
                            float xk = (lk & m) ? v[jj] : v[m + jj];
                            float r  = __shfl_xor_sync(0xffffffffu, xk, m);
                            v[jj] = fmaxf((lk & m) ? v[m + jj] : v[jj], r);
                        }
                    }
                    s_pool[g * 256 + wig * 128 + tile * 32 + lk] = v[0];
                }
            }
            NAMED_BAR(1 + g);
            if (sq < SS) {
                int gq = b * SS + sq;
                float* pl = s_pool + g * 256;
                out[(size_t)gq * CO + k]      = fmaxf(pl[k],      pl[128 + k]);
                out[(size_t)gq * CO + 64 + k] = fmaxf(pl[64 + k], pl[192 + k]);
            }
            NAMED_BAR(1 + g);
        }
        __syncthreads();
    }
}

// =====================================================================
// launch
// =====================================================================
extern "C" void kernel_launch(void* const* d_in, const int* in_sizes, int n_in,
                              void* d_out, int out_size)
{
    const float* x   = (const float*)d_in[0];
    const float* pos = (const float*)d_in[1];
    const float* W1  = (const float*)d_in[2];
    const float* b1  = (const float*)d_in[3];
    const float* W2  = (const float*)d_in[4];
    const float* b2  = (const float*)d_in[5];
    const float* W3  = (const float*)d_in[6];
    const float* b3  = (const float*)d_in[7];

    float* out = (float*)d_out;
    float* nxyz;
    if (out_size >= BB * SS * CO + BB * SS * 3) {
        nxyz = out + (size_t)BB * SS * CO;
    } else {
        cudaGetSymbolAddress((void**)&nxyz, g_nxyz_fallback);
    }

    const int smem = SMEM_FLOATS * (int)sizeof(float);   // ~120 KB
    cudaFuncSetAttribute(fused_kernel, cudaFuncAttributeMaxDynamicSharedMemorySize,
                         smem);

    fused_kernel<<<BB + NWORKB, 256, smem>>>(x, pos, W1, b1, W2, b2, W3, b3,
                                             out, nxyz);
}

// round 11
// speedup vs baseline: 1.4033x; 1.0017x over previous
#include <cuda_runtime.h>
#include <cstdint>

#define BB 8
#define NN 4096
#define DD 64
#define SS 1024
#define KK 64
#define HH 64
#define CO 128
#define NWORKB 140     // worker blocks; first 136 also do BQ+MLP
#define WPB 17         // query-workers per batch

typedef unsigned long long u64;

// -------- device scratch --------
__device__ int   g_fps[BB * SS];
__device__ int   g_prog[BB];
__device__ int   g_feat_done;
__device__ float g_T[BB * NN * HH];
__device__ float g_nxyz_fallback[BB * SS * 3];

// -------- smem layout (floats) --------
#define OFF_C4   0       // 4096 float4 = 16384 floats
#define OFF_RED  16384   // 64 uints (2x8 parity, v+i)
#define OFF_W1X  16448   // 192
#define OFF_W2   16640   // 4096 (feat phase reuses as W1[3:])
#define OFF_W3   20736   // 8192
#define OFF_B2   28928   // 64 (feat phase reuses as b1)
#define OFF_B3   28992   // 128
#define OFF_NBRI 29120   // 512 ints (8 warps x 64)
#define OFF_CNT  29632   // 8
#define OFF_QXYZ 29640   // 24
#define OFF_POOL 29664   // 1024 (4 groups x 256)
#define SMEM_FLOATS 30688

// ---------------- helpers ----------------
__device__ __forceinline__ u64 pk2(float lo, float hi) {
    u64 d; asm("mov.b64 %0, {%1, %2};" : "=l"(d) : "f"(lo), "f"(hi)); return d;
}
__device__ __forceinline__ void upk2(u64 v, float& lo, float& hi) {
    asm("mov.b64 {%0, %1}, %2;" : "=f"(lo), "=f"(hi) : "l"(v));
}
__device__ __forceinline__ u64 fma2(u64 a, u64 b, u64 c) {
    u64 d; asm("fma.rn.f32x2 %0, %1, %2, %3;" : "=l"(d) : "l"(a), "l"(b), "l"(c));
    return d;
}
__device__ __forceinline__ u64 add2(u64 a, u64 b) {
    u64 d; asm("add.rn.f32x2 %0, %1, %2;" : "=l"(d) : "l"(a), "l"(b)); return d;
}
__device__ __forceinline__ u64 mul2(u64 a, u64 b) {
    u64 d; asm("mul.rn.f32x2 %0, %1, %2;" : "=l"(d) : "l"(a), "l"(b)); return d;
}
__device__ __forceinline__ unsigned redux_max_u32(unsigned v) {
    unsigned d; asm("redux.sync.max.u32 %0, %1, 0xffffffff;" : "=r"(d) : "r"(v)); return d;
}
__device__ __forceinline__ unsigned redux_min_u32(unsigned v) {
    unsigned d; asm("redux.sync.min.u32 %0, %1, 0xffffffff;" : "=r"(d) : "r"(v)); return d;
}
__device__ __forceinline__ void st_release(int* p, int v) {
    asm volatile("st.release.gpu.s32 [%0], %1;" :: "l"(p), "r"(v) : "memory");
}
__device__ __forceinline__ int ld_acquire(const int* p) {
    int v; asm volatile("ld.acquire.gpu.s32 %0, [%1];" : "=r"(v) : "l"(p) : "memory");
    return v;
}
#define NAMED_BAR(id) asm volatile("bar.sync %0, 64;" :: "r"(id) : "memory")

// =====================================================================
// Fused persistent kernel. grid = 148 (one wave), block = 256.
// blocks 0..7   : FPS producer (one batch each), publishes via g_prog
// blocks 8..147 : feat hoist, then (first 136) BQ+MLP consumers
// =====================================================================
__global__ __launch_bounds__(256, 1) void fused_kernel(
    const float* __restrict__ x,  const float* __restrict__ pos,
    const float* __restrict__ W1, const float* __restrict__ b1,
    const float* __restrict__ W2, const float* __restrict__ b2,
    const float* __restrict__ W3, const float* __restrict__ b3,
    float* __restrict__ out, float* __restrict__ nxyz)
{
    extern __shared__ float sm[];
    int t = threadIdx.x, lane = t & 31, warp = t >> 5;

    if (blockIdx.x < BB) {
        // =========================== FPS ===========================
        int b = blockIdx.x;
        const float* p = pos + (size_t)b * NN * 3;
        float4* c4 = (float4*)(sm + OFF_C4);
        unsigned* s_v = (unsigned*)(sm + OFF_RED);   // [2][8] parity
        unsigned* s_i = s_v + 16;

        for (int i = t; i < NN * 3; i += 256) {
            float v = p[i]; int n = i / 3, c = i - n * 3;
            ((float*)c4)[n * 4 + c] = v;
        }
        __syncthreads();

        const int base = t * 16;
        u64 cpx[8], cpy[8], cpz[8];
        float md[16];
#pragma unroll
        for (int q = 0; q < 8; q++) {
            float4 p0 = c4[base + 2 * q];
            float4 p1 = c4[base + 2 * q + 1];
            cpx[q] = pk2(p0.x, p1.x);
            cpy[q] = pk2(p0.y, p1.y);
            cpz[q] = pk2(p0.z, p1.z);
        }
#pragma unroll
        for (int r = 0; r < 16; r++) md[r] = 1e10f;

        if (t == 0) {
            g_fps[b * SS] = 0;
            st_release(&g_prog[b], 0);
        }
        int last = 0;

        for (int s = 1; s < SS; s++) {
            float4 lp = c4[last];                 // ONE dependent LDS.128
            u64 nlx = pk2(-lp.x, -lp.x), nly = pk2(-lp.y, -lp.y),
                nlz = pk2(-lp.z, -lp.z);
#pragma unroll
            for (int q = 0; q < 8; q++) {
                // exact reference rounding: sub, square, ((xx+yy)+zz); no fma
                u64 dx = add2(cpx[q], nlx);
                u64 dy = add2(cpy[q], nly);
                u64 dz = add2(cpz[q], nlz);
                u64 d2 = add2(add2(mul2(dx, dx), mul2(dy, dy)), mul2(dz, dz));
                float dlo, dhi; upk2(d2, dlo, dhi);
                md[2 * q]     = fminf(md[2 * q], dlo);
                md[2 * q + 1] = fminf(md[2 * q + 1], dhi);
            }
            // shallow tree max + parallel index recovery
            float m01[8];
#pragma unroll
            for (int q = 0; q < 8; q++) m01[q] = fmaxf(md[2 * q], md[2 * q + 1]);
            float a0 = fmaxf(m01[0], m01[1]), a1 = fmaxf(m01[2], m01[3]);
            float a2 = fmaxf(m01[4], m01[5]), a3 = fmaxf(m01[6], m01[7]);
            float best = fmaxf(fmaxf(a0, a1), fmaxf(a2, a3));
            unsigned msk = 0;
#pragma unroll
            for (int r = 0; r < 16; r++) if (md[r] == best) msk |= (1u << r);
            int bi = base + __ffs(msk) - 1;

            int par = s & 1;
            unsigned vb = __float_as_uint(best);        // dist >= 0: bits monotonic
            unsigned mx = redux_max_u32(vb);
            unsigned ci = (vb == mx) ? (unsigned)bi : 0xffffffffu;
            unsigned mn = redux_min_u32(ci);
            if (lane == 0) { s_v[par * 8 + warp] = mx; s_i[par * 8 + warp] = mn; }
            __syncthreads();
            unsigned v2 = (lane < 8) ? s_v[par * 8 + lane] : 0u;
            unsigned i2 = (lane < 8) ? s_i[par * 8 + lane] : 0xffffffffu;
            unsigned m2 = redux_max_u32(v2);
            unsigned c2 = (v2 == m2) ? i2 : 0xffffffffu;
            last = (int)redux_min_u32(c2);
            if (t == 0) {
                g_fps[b * SS + s] = last;
                st_release(&g_prog[b], s);
            }
        }
        return;
    }

    // =========================== workers ===========================
    int wb = blockIdx.x - BB;   // 0..139

    // ---- phase 1: feat hoist T = x @ W1[3:,:] + b1 ----
    {
        float* sW = sm + OFF_W2;
        float* sbF = sm + OFF_B2;
        for (int i = t; i < DD * HH; i += 256) sW[i] = W1[3 * HH + i];
        if (t < HH) sbF[t] = b1[t];
        __syncthreads();

        for (int n = wb * 8 + warp; n < BB * NN; n += NWORKB * 8) {
            const float* xr = x + (size_t)n * DD;
            float xr0 = xr[lane];
            float xr1 = xr[lane + 32];
            float a0 = sbF[lane], a1 = sbF[lane + 32];
#pragma unroll
            for (int d = 0; d < 32; d++) {
                float xv = __shfl_sync(0xffffffffu, xr0, d);
                a0 += xv * sW[d * HH + lane];
                a1 += xv * sW[d * HH + 32 + lane];
            }
#pragma unroll
            for (int d = 0; d < 32; d++) {
                float xv = __shfl_sync(0xffffffffu, xr1, d);
                a0 += xv * sW[(32 + d) * HH + lane];
                a1 += xv * sW[(32 + d) * HH + 32 + lane];
            }
            g_T[(size_t)n * HH + lane]      = a0;
            g_T[(size_t)n * HH + 32 + lane] = a1;
        }
        __threadfence();
        __syncthreads();
        if (t == 0) atomicAdd(&g_feat_done, 1);
    }

    if (wb >= BB * WPB) return;   // 4 feat-only blocks retire

    int b = wb / WPB;
    int w = wb % WPB;

    // ---- phase 2: load cloud (float4) + MLP weights ----
    float4* c4 = (float4*)(sm + OFF_C4);
    {
        const float* p = pos + (size_t)b * NN * 3;
        for (int i = t; i < NN * 3; i += 256) {
            float v = p[i]; int n = i / 3, c = i - n * 3;
            ((float*)c4)[n * 4 + c] = v;
        }
    }
    float* sW1x = sm + OFF_W1X;
    float* sW2  = sm + OFF_W2;
    float* sW3  = sm + OFF_W3;
    float* sb2  = sm + OFF_B2;
    float* sb3  = sm + OFF_B3;
    for (int i = t; i < 192;  i += 256) sW1x[i] = W1[i];
    for (int i = t; i < 4096; i += 256) sW2[i]  = W2[i];
    for (int i = t; i < 8192; i += 256) sW3[i]  = W3[i];
    if (t < 64)                sb2[t] = b2[t];
    if (t >= 64 && t < 192)    sb3[t - 64] = b3[t - 64];
    __syncthreads();
    if (t == 0) {
        while (ld_acquire(&g_feat_done) < NWORKB) { __nanosleep(256); }
    }
    __syncthreads();

    int*   s_nbr  = (int*)(sm + OFF_NBRI);
    int*   s_cnt  = (int*)(sm + OFF_CNT);
    float* s_qxyz = sm + OFF_QXYZ;
    float* s_pool = sm + OFF_POOL;
    const float RR = (float)(0.2 * 0.2);

    int g   = t >> 6;       // MLP group 0..3
    int k   = t & 63;       // neighbor slot
    int lk  = k & 31;
    int wig = k >> 5;

    for (int j = 0; j < 8; j++) {
        // ---- BQ: warp per query (8 queries per round) ----
        int sQ = w + WPB * (8 * j + warp);
        if (sQ < SS) {
            if (lane == 0) {
                while (ld_acquire(&g_prog[b]) < sQ) { __nanosleep(128); }
            }
            __syncwarp();
            int qi = 0;
            if (lane == 0) qi = ld_acquire(&g_fps[b * SS + sQ]);
            qi = __shfl_sync(0xffffffffu, qi, 0);
            float4 qp = c4[qi];
            float qx = qp.x, qy = qp.y, qz = qp.z;
            if (lane == 0) {
                s_qxyz[warp * 3 + 0] = qx;
                s_qxyz[warp * 3 + 1] = qy;
                s_qxyz[warp * 3 + 2] = qz;
                int gq = b * SS + sQ;
                nxyz[gq * 3 + 0] = qx;
                nxyz[gq * 3 + 1] = qy;
                nxyz[gq * 3 + 2] = qz;
            }
            int count = 0;
            for (int c = 0; c < NN / 32; c++) {
                int i = c * 32 + lane;
                float4 pv = c4[i];
                float dx = pv.x - qx, dy = pv.y - qy, dz = pv.z - qz;
                float d2 = __fadd_rn(__fadd_rn(__fmul_rn(dx, dx), __fmul_rn(dy, dy)),
                                     __fmul_rn(dz, dz));
                bool hit = d2 < RR;
                unsigned m = __ballot_sync(0xffffffffu, hit);
                if (hit) {
                    int ofs = count + __popc(m & ((1u << lane) - 1u));
                    if (ofs < KK) s_nbr[warp * KK + ofs] = i;
                }
                count += __popc(m);
                if (count >= KK) break;
            }
            if (count > KK) count = KK;
            if (lane == 0) s_cnt[warp] = count;
            for (int q2 = count + lane; q2 < KK; q2 += 32) s_nbr[warp * KK + q2] = NN - 1;
        }
        __syncthreads();

        // ---- MLP: 2 sub-rounds x 4 groups of 64 threads ----
        for (int sub = 0; sub < 2; sub++) {
            int ql = sub * 4 + g;
            int sq = w + WPB * (8 * j + ql);
            if (sq < SS) {
                int cnt = s_cnt[ql];
                int n   = s_nbr[ql * KK + k];
                bool valid = (k < cnt);
                float qx = s_qxyz[ql * 3 + 0];
                float qy = s_qxyz[ql * 3 + 1];
                float qz = s_qxyz[ql * 3 + 2];
                float4 pn = c4[n];
                float dx = pn.x - qx, dy = pn.y - qy, dz = pn.z - qz;

                // layer 1
                u64 hp[32];
                const ulonglong2* Trow =
                    (const ulonglong2*)(g_T + ((size_t)(b * NN + n)) * HH);
#pragma unroll
                for (int q = 0; q < 16; q++) {
                    ulonglong2 v = Trow[q];
                    hp[2 * q] = v.x; hp[2 * q + 1] = v.y;
                }
                {
                    u64 dx2 = pk2(dx, dx), dy2 = pk2(dy, dy), dz2 = pk2(dz, dz);
                    const u64* w0 = (const u64*)(sW1x);
                    const u64* w1 = (const u64*)(sW1x + 64);
                    const u64* w2 = (const u64*)(sW1x + 128);
#pragma unroll
                    for (int jj = 0; jj < 32; jj++) {
                        hp[jj] = fma2(dx2, w0[jj], hp[jj]);
                        hp[jj] = fma2(dy2, w1[jj], hp[jj]);
                        hp[jj] = fma2(dz2, w2[jj], hp[jj]);
                    }
                }
                float h1[64];
#pragma unroll
                for (int jj = 0; jj < 32; jj++) {
                    float lo, hi; upk2(hp[jj], lo, hi);
                    h1[2 * jj]     = fmaxf(lo, 0.0f);
                    h1[2 * jj + 1] = fmaxf(hi, 0.0f);
                }

                // layer 2
                u64 acc[32];
#pragma unroll
                for (int jj = 0; jj < 32; jj++)
                    acc[jj] = pk2(sb2[2 * jj], sb2[2 * jj + 1]);
#pragma unroll 8
                for (int i = 0; i < 64; i++) {
                    u64 a2 = pk2(h1[i], h1[i]);
                    const ulonglong2* ww = (const ulonglong2*)(sW2 + i * 64);
#pragma unroll
                    for (int q = 0; q < 16; q++) {
                        ulonglong2 wv = ww[q];
                        acc[2 * q]     = fma2(a2, wv.x, acc[2 * q]);
                        acc[2 * q + 1] = fma2(a2, wv.y, acc[2 * q + 1]);
                    }
                }
                float h2[64];
#pragma unroll
                for (int jj = 0; jj < 32; jj++) {
                    float lo, hi; upk2(acc[jj], lo, hi);
                    h2[2 * jj]     = fmaxf(lo, 0.0f);
                    h2[2 * jj + 1] = fmaxf(hi, 0.0f);
                }

                // layer 3 + masked distributed max-pool
                for (int tile = 0; tile < 4; tile++) {
                    u64 a3[16];
                    const float* bt = sb3 + tile * 32;
#pragma unroll
                    for (int jj = 0; jj < 16; jj++)
                        a3[jj] = pk2(bt[2 * jj], bt[2 * jj + 1]);
#pragma unroll 8
                    for (int i = 0; i < 64; i++) {
                        u64 a2 = pk2(h2[i], h2[i]);
                        const ulonglong2* ww =
                            (const ulonglong2*)(sW3 + i * CO + tile * 32);
#pragma unroll
                        for (int q = 0; q < 8; q++) {
                            ulonglong2 wv = ww[q];
                            a3[2 * q]     = fma2(a2, wv.x, a3[2 * q]);
                            a3[2 * q + 1] = fma2(a2, wv.y, a3[2 * q + 1]);
                        }
                    }
                    float v[32];
#pragma unroll
                    for (int jj = 0; jj < 16; jj++) {
                        float lo, hi; upk2(a3[jj], lo, hi);
                        v[2 * jj]     = valid ? lo : 0.0f;
                        v[2 * jj + 1] = valid ? hi : 0.0f;
                    }
#pragma unroll
                    for (int m = 16; m >= 1; m >>= 1) {
#pragma unroll 16
                        for (int jj = 0; jj < m; jj++) {
                            float xk = (lk & m) ? v[jj] : v[m + jj];
                            float r  = __shfl_xor_sync(0xffffffffu, xk, m);
                            v[jj] = fmaxf((lk & m) ? v[m + jj] : v[jj], r);
                        }
                    }
                    s_pool[g * 256 + wig * 128 + tile * 32 + lk] = v[0];
                }
            }
            NAMED_BAR(1 + g);
            if (sq < SS) {
                int gq = b * SS + sq;
                float* pl = s_pool + g * 256;
                out[(size_t)gq * CO + k]      = fmaxf(pl[k],      pl[128 + k]);
                out[(size_t)gq * CO + 64 + k] = fmaxf(pl[64 + k], pl[192 + k]);
            }
            NAMED_BAR(1 + g);
        }
        __syncthreads();
    }
}

// =====================================================================
// launch
// =====================================================================
extern "C" void kernel_launch(void* const* d_in, const int* in_sizes, int n_in,
                              void* d_out, int out_size)
{
    const float* x   = (const float*)d_in[0];
    const float* pos = (const float*)d_in[1];
    const float* W1  = (const float*)d_in[2];
    const float* b1  = (const float*)d_in[3];
    const float* W2  = (const float*)d_in[4];
    const float* b2  = (const float*)d_in[5];
    const float* W3  = (const float*)d_in[6];
    const float* b3  = (const float*)d_in[7];

    float* out = (float*)d_out;
    float* nxyz;
    if (out_size >= BB * SS * CO + BB * SS * 3) {
        nxyz = out + (size_t)BB * SS * CO;
    } else {
        cudaGetSymbolAddress((void**)&nxyz, g_nxyz_fallback);
    }

    const int smem = SMEM_FLOATS * (int)sizeof(float);   // ~120 KB
    cudaFuncSetAttribute(fused_kernel, cudaFuncAttributeMaxDynamicSharedMemorySize,
                         smem);

    fused_kernel<<<BB + NWORKB, 256, smem>>>(x, pos, W1, b1, W2, b2, W3, b3,
                                             out, nxyz);
}